// round 17
// baseline (speedup 1.0000x reference)
#include <cuda_runtime.h>
#include <cuda_bf16.h>
#include <cstdint>

#define C_CLASSES 50000
#define C_PAD     50176            // 392 * 128 = 1568 * 32
#define B_N       512
#define D_DIM     128
#define K2F       46.166241308446828f   // 32 * log2(e)
#define MRGF      0.1f
#define P_BLOCKS  1568             // pnorm blocks in k_prep
#define X_BLOCKS  256              // xnorm/zero blocks in k_prep

// ---------------- device scratch (static, no runtime alloc) ----------------
__device__ __align__(16) float          g_Xn[B_N * D_DIM];
__device__ __align__(16) __nv_bfloat16  g_Xn_bf[B_N * D_DIM];
__device__ __align__(16) __nv_bfloat16  g_Pn_bf[C_PAD * D_DIM];   // ~12.8 MB
__device__ float g_center_sim[C_CLASSES];
__device__ float g_cterm[C_PAD];     // K2 * (mrg + adj), log2 units
__device__ float g_Nbuf[C_PAD];      // UNSCALED: sum_b exp2(K2*cos) minus one-hot
__device__ float g_Pbuf[C_CLASSES];  // UNSCALED: sum onehot exp2(-K2*cos)
__device__ float g_abspart[P_BLOCKS];// per-block |centers| partials (overwrite, no zero)
__device__ float g_acc[4];           // [0]=posAcc, [1]=negAcc, [2]=absAcc
__device__ int   g_num_valid;
__device__ int   g_done;
__device__ int   g_ph1;
__device__ int   g_ph2;

__device__ __forceinline__ float ex2f(float x) {
    float y;
    asm("ex2.approx.ftz.f32 %0, %1;" : "=f"(y) : "f"(x));
    return y;
}

__device__ __forceinline__ float wred(float v) {
#pragma unroll
    for (int o = 16; o; o >>= 1) v += __shfl_xor_sync(0xffffffffu, v, o);
    return v;
}

template<int N>
__device__ __forceinline__ void wredN(float* v) {
#pragma unroll
    for (int o = 16; o; o >>= 1)
#pragma unroll
        for (int i = 0; i < N; i++)
            v[i] += __shfl_xor_sync(0xffffffffu, v[i], o);
}

__device__ __forceinline__ unsigned smem_u32(const void* p) {
    unsigned a;
    asm("{ .reg .u64 t; cvta.to.shared.u64 t, %1; cvt.u32.u64 %0, t; }"
        : "=r"(a) : "l"(p));
    return a;
}

// ---------------- kernel PREP: pnorm blocks || xnorm+zero blocks -----------
// Blocks 0..1567: proxy normalize -> bf16, center_sim, |c| partial.
// Blocks 1568..1823: zero class buffers + normalize X (2 rows/block).
// The two halves are fully independent (no slot scratch anymore).
__global__ __launch_bounds__(256) void k_prep(const float* __restrict__ X,
                                              const float* __restrict__ proxies,
                                              const float* __restrict__ centers) {
    __shared__ float shm[8];
    const int tid = threadIdx.x;

    if (blockIdx.x < P_BLOCKS) {
        // ---------------- pnorm half ----------------
        const int warp = tid >> 5, lane = tid & 31;
        const int r0 = (blockIdx.x * 8 + warp) * 4;
        if (tid == 0) shm[0] = 0.f;
        __syncthreads();

        const float4 z4 = make_float4(0.f, 0.f, 0.f, 0.f);
        float4 p[4], c4[4];
#pragma unroll
        for (int i = 0; i < 4; i++) {
            int r = r0 + i;
            p[i]  = (r < C_CLASSES)
                  ? reinterpret_cast<const float4*>(proxies + (size_t)r * D_DIM)[lane] : z4;
        }
#pragma unroll
        for (int i = 0; i < 4; i++) {
            int r = r0 + i;
            c4[i] = (r < C_CLASSES)
                  ? reinterpret_cast<const float4*>(centers + (size_t)r * D_DIM)[lane] : z4;
        }

        float ss[4];
#pragma unroll
        for (int i = 0; i < 4; i++)
            ss[i] = p[i].x * p[i].x + p[i].y * p[i].y + p[i].z * p[i].z + p[i].w * p[i].w;
        wredN<4>(ss);

        float inv[4];
#pragma unroll
        for (int i = 0; i < 4; i++) inv[i] = rsqrtf(ss[i] + 1e-12f);

#pragma unroll
        for (int i = 0; i < 4; i++) {
            __nv_bfloat162 w0 = __floats2bfloat162_rn(p[i].x * inv[i], p[i].y * inv[i]);
            __nv_bfloat162 w1 = __floats2bfloat162_rn(p[i].z * inv[i], p[i].w * inv[i]);
            uint2 pk = make_uint2(*reinterpret_cast<unsigned*>(&w0),
                                  *reinterpret_cast<unsigned*>(&w1));
            reinterpret_cast<uint2*>(g_Pn_bf + (size_t)(r0 + i) * D_DIM)[lane] = pk;
        }

        float dca[8];
        float abt = 0.f;
#pragma unroll
        for (int i = 0; i < 4; i++) {
            dca[i]     = inv[i] * (p[i].x * c4[i].x + p[i].y * c4[i].y +
                                   p[i].z * c4[i].z + p[i].w * c4[i].w);
            dca[4 + i] = c4[i].x * c4[i].x + c4[i].y * c4[i].y +
                         c4[i].z * c4[i].z + c4[i].w * c4[i].w;
            abt += fabsf(c4[i].x) + fabsf(c4[i].y) + fabsf(c4[i].z) + fabsf(c4[i].w);
        }
        wredN<8>(dca);
        abt = wred(abt);

        if (lane == 0) {
#pragma unroll
            for (int i = 0; i < 4; i++) {
                int r = r0 + i;
                if (r < C_CLASSES) {
                    float pn2   = ss[i] * inv[i] * inv[i];
                    float pnorm = fmaxf(sqrtf(pn2), 1e-8f);
                    float cnorm = fmaxf(sqrtf(dca[4 + i]), 1e-8f);
                    g_center_sim[r] = dca[i] / (pnorm * cnorm);
                }
                g_cterm[r] = K2F * MRGF;             // default: adj = 0
            }
            atomicAdd(&shm[0], abt);
        }
        __syncthreads();
        if (tid == 0) g_abspart[blockIdx.x] = shm[0];
    } else {
        // ---------------- xnorm + zero half ----------------
        const int bid2 = blockIdx.x - P_BLOCKS;      // 0..255
        const int j = bid2 * 256 + tid;              // 0..65535
        if (j < C_PAD)     g_Nbuf[j] = 0.f;
        if (j < C_CLASSES) g_Pbuf[j] = 0.f;
        if (j < 4)         g_acc[j]  = 0.f;
        if (j == 0) { g_num_valid = 0; g_done = 0; g_ph1 = 0; g_ph2 = 0; }

        const int hb = tid >> 7, d = tid & 127;
        const int row = bid2 * 2 + hb;               // 512 rows
        float x = X[row * D_DIM + d];
        float v = wred(x * x);
        if ((d & 31) == 0) shm[hb * 4 + (d >> 5)] = v;
        __syncthreads();
        float ss = shm[hb * 4] + shm[hb * 4 + 1] + shm[hb * 4 + 2] + shm[hb * 4 + 3]
                 + 1e-12f;
        float y = x * rsqrtf(ss);
        g_Xn[row * D_DIM + d]    = y;
        g_Xn_bf[row * D_DIM + d] = __float2bfloat16(y);
    }
}

// ---------------- kernel GF: GEMM + barrier + statfin(scan) + reduce + final
// Mainloop byte-identical to R14/R16 best (legacy-HMMA rate floor ~90% sat).
// All 392 blocks resident (launch_bounds(256,3): regs<=85, smem 209KB/SM).
__global__ __launch_bounds__(256, 3) void k_gemmfinal(const int* __restrict__ T,
                                                      const float* __restrict__ proxies,
                                                      float* __restrict__ out) {
    extern __shared__ __align__(16) unsigned char smraw[];
    __nv_bfloat16* sA = reinterpret_cast<__nv_bfloat16*>(smraw);  // [256][136]
    const int tid = threadIdx.x, wid = tid >> 5, lane = tid & 31;
    const int tile = blockIdx.x;                 // 0..391
    const int cbase = tile * 128 + wid * 16;

    const int tg = lane & 3, g = lane >> 2;

    unsigned br[2][8][2];
#pragma unroll
    for (int t = 0; t < 2; t++) {
        const __nv_bfloat16* rowp = g_Pn_bf + (size_t)(cbase + t * 8 + g) * D_DIM;
#pragma unroll
        for (int ks = 0; ks < 8; ks++) {
            br[t][ks][0] = *reinterpret_cast<const unsigned*>(rowp + ks * 16 + tg * 2);
            br[t][ks][1] = *reinterpret_cast<const unsigned*>(rowp + ks * 16 + 8 + tg * 2);
        }
    }
    float ns[2][2] = {};

    const unsigned sbase = smem_u32(sA);
    const int sub = lane >> 3, rl = lane & 7;
    const int row_off = rl + ((sub & 1) << 3);
    const int k_off   = (sub >> 1) << 3;

    for (int half = 0; half < 2; half++) {
        __syncthreads();
        for (int i = tid; i < 256 * 16; i += 256) {
            int r = i >> 4, q = i & 15;
            uint4 v = *reinterpret_cast<const uint4*>(
                g_Xn_bf + (half * 256 + r) * D_DIM + q * 8);
            *reinterpret_cast<uint4*>(sA + r * 136 + q * 8) = v;
        }
        __syncthreads();

        unsigned maddr = sbase + (unsigned)((row_off * 136 + k_off) * 2);
        for (int m = 0; m < 16; m++) {
            float acc[2][4] = {};
            unsigned a[2][4];
            asm volatile("ldmatrix.sync.aligned.m8n8.x4.shared.b16 {%0,%1,%2,%3}, [%4];"
                         : "=r"(a[0][0]), "=r"(a[0][1]), "=r"(a[0][2]), "=r"(a[0][3])
                         : "r"(maddr));
#pragma unroll
            for (int ks = 0; ks < 8; ks++) {
                if (ks < 7) {
                    unsigned* an = a[(ks + 1) & 1];
                    asm volatile("ldmatrix.sync.aligned.m8n8.x4.shared.b16 {%0,%1,%2,%3}, [%4];"
                                 : "=r"(an[0]), "=r"(an[1]), "=r"(an[2]), "=r"(an[3])
                                 : "r"(maddr + (unsigned)((ks + 1) * 32)));
                }
                const unsigned* ac = a[ks & 1];
#pragma unroll
                for (int t = 0; t < 2; t++) {
                    asm("mma.sync.aligned.m16n8k16.row.col.f32.bf16.bf16.f32 "
                        "{%0,%1,%2,%3}, {%4,%5,%6,%7}, {%8,%9}, {%0,%1,%2,%3};"
                        : "+f"(acc[t][0]), "+f"(acc[t][1]), "+f"(acc[t][2]), "+f"(acc[t][3])
                        : "r"(ac[0]), "r"(ac[1]), "r"(ac[2]), "r"(ac[3]),
                          "r"(br[t][ks][0]), "r"(br[t][ks][1]));
                }
            }
            maddr += 16 * 272;
#pragma unroll
            for (int t = 0; t < 2; t++) {
                ns[t][0] += ex2f(acc[t][0] * K2F) + ex2f(acc[t][2] * K2F);
                ns[t][1] += ex2f(acc[t][1] * K2F) + ex2f(acc[t][3] * K2F);
            }
        }
    }
#pragma unroll
    for (int o = 4; o < 32; o <<= 1)
#pragma unroll
        for (int t = 0; t < 2; t++)
#pragma unroll
            for (int j = 0; j < 2; j++)
                ns[t][j] += __shfl_xor_sync(0xffffffffu, ns[t][j], o);

    if (g == 0) {
#pragma unroll
        for (int t = 0; t < 2; t++)
#pragma unroll
            for (int j = 0; j < 2; j++)
                atomicAdd(&g_Nbuf[cbase + t * 8 + tg * 2 + j], ns[t][j]);
    }

    // ---- grid barrier 1: all 392 blocks (Nbuf complete) ----
    __syncthreads();
    if (tid == 0) {
        __threadfence();
        atomicAdd(&g_ph1, 1);
        while (*(volatile int*)&g_ph1 < 392) { }
    }
    __syncthreads();
    __threadfence();
    if (blockIdx.x >= 256) return;               // extra blocks done

    // tail smem layout inside smraw (sA dead after barrier)
    int*   Ts  = reinterpret_cast<int*>(smraw);          // [512]
    float* s1  = reinterpret_cast<float*>(smraw + 2048); // [8]
    float* s2  = s1 + 8;                                  // [8]
    float* red = s2 + 8;                                  // [8]
    float* sn  = red + 8;                                 // [8]
    float* sp2 = sn + 8;                                  // [8]
    float* sb  = sp2 + 8;                                 // [8]

    Ts[tid]       = T[tid];
    Ts[tid + 256] = T[tid + 256];
    __syncthreads();

    // ---- phase 1: one-hot exp terms + stats-by-scan -> cterm (2 rows/blk) -
    const int hb = tid >> 7, d = tid & 127;
    const int b = blockIdx.x * 2 + hb;
    const int c = Ts[b];

    const float* pr = proxies + (size_t)c * D_DIM;
    float p = pr[d];
    float v = wred(p * p);
    if ((d & 31) == 0) s1[hb * 4 + (d >> 5)] = v;
    __syncthreads();
    float ssq = s1[hb * 4] + s1[hb * 4 + 1] + s1[hb * 4 + 2] + s1[hb * 4 + 3];
    float inv = 1.0f / sqrtf(ssq + 1e-12f);
    float x = g_Xn[b * D_DIM + d];
    float v2 = wred(x * (p * inv));
    if ((d & 31) == 0) s2[hb * 4 + (d >> 5)] = v2;
    __syncthreads();
    if (d == 0) {
        float cosv = s2[hb * 4] + s2[hb * 4 + 1] + s2[hb * 4 + 2] + s2[hb * 4 + 3];
        atomicAdd(&g_Nbuf[c], -ex2f(K2F * cosv));
        atomicAdd(&g_Pbuf[c],  ex2f(-K2F * cosv));
    }

    // stats by direct scan of T (class multiplicity ~1; rep = min-row owner)
    int n = 0, minrow = b;
    float s = 0.f, s2v = 0.f;
    for (int i = 0; i < B_N; i++) {
        if (Ts[i] == c) {
            n++;
            if (i < minrow) minrow = i;
            float xv = g_Xn[i * D_DIM + d];
            s += xv; s2v += xv * xv;
        }
    }
    float fn = (float)n;
    float mean = s / fn;
    float var  = s2v / fn - mean * mean;
    var = fminf(fmaxf(var, 1e-6f), 10.0f);
    float vv = wred(var);
    if ((d & 31) == 0) red[hb * 4 + (d >> 5)] = vv;
    __syncthreads();
    if (minrow == b && d == 0) {
        float vmean = (red[hb * 4] + red[hb * 4 + 1] + red[hb * 4 + 2] + red[hb * 4 + 3])
                    * (1.0f / 128.0f);
        float vw  = 1.0f / (1.0f + vmean);
        float adj = g_center_sim[c] * vw * 0.15f;
        g_cterm[c] = K2F * (MRGF + adj);
        atomicAdd(&g_num_valid, 1);
    }

    // ---- grid barrier 2: blocks 0..255 (cterm/Nbuf/Pbuf complete) ----
    __syncthreads();
    if (tid == 0) {
        __threadfence();
        atomicAdd(&g_ph2, 1);
        while (*(volatile int*)&g_ph2 < 256) { }
    }
    __syncthreads();
    __threadfence();

    // ---- phase 2: scaled log1p sums + abspart sum + final combine ----
    int i = blockIdx.x * 256 + tid;              // covers 65536 >= C_CLASSES
    float nl = 0.f, pl = 0.f;
    if (i < C_CLASSES) {
        float ctm = g_cterm[i];
        nl = log1pf(fmaxf(ex2f(ctm) * g_Nbuf[i], 0.f));
        pl = log1pf(ex2f(2.0f * K2F * MRGF - ctm) * g_Pbuf[i]);
    }
    float ab = (i < P_BLOCKS) ? g_abspart[i] : 0.f;
    float aa = wred(nl);
    float b2 = wred(pl);
    float a3 = wred(ab);
    int w = tid >> 5, l = tid & 31;
    if (l == 0) { sn[w] = aa; sp2[w] = b2; sb[w] = a3; }
    __syncthreads();
    if (tid == 0) {
        float tn = 0.f, tp = 0.f, tb = 0.f;
#pragma unroll
        for (int k = 0; k < 8; k++) { tn += sn[k]; tp += sp2[k]; tb += sb[k]; }
        atomicAdd(&g_acc[1], tn);
        atomicAdd(&g_acc[0], tp);
        atomicAdd(&g_acc[2], tb);
        __threadfence();
        int prev = atomicAdd(&g_done, 1);
        if (prev == 255) {
            volatile float* ac = g_acc;
            float pos = ac[0] / (float)g_num_valid;
            float neg = ac[1] * (1.0f / 50000.0f);
            float reg = ac[2] * (1.0f / (50000.0f * 128.0f));
            out[0] = pos + neg + 0.01f * reg;
        }
    }
}

// ---------------- launch: 2 kernels ----------------------------------------
extern "C" void kernel_launch(void* const* d_in, const int* in_sizes, int n_in,
                              void* d_out, int out_size) {
    const float* X       = (const float*)d_in[0];
    const int*   T       = (const int*)d_in[1];
    const float* proxies = (const float*)d_in[2];
    const float* centers = (const float*)d_in[3];
    float* out = (float*)d_out;

    const int gemm_smem = 256 * 136 * 2;   // 69632 B dynamic smem
    cudaFuncSetAttribute(k_gemmfinal, cudaFuncAttributeMaxDynamicSharedMemorySize,
                         gemm_smem);

    k_prep     <<<P_BLOCKS + X_BLOCKS, 256>>>(X, proxies, centers);
    k_gemmfinal<<<392, 256, gemm_smem>>>(T, proxies, out);
}